// round 2
// baseline (speedup 1.0000x reference)
#include <cuda_runtime.h>

#define BB 64
#define NN 576
#define DD 768
#define KK 1024
#define NT 2
#define ROWS (BB * NN)          // 36864
#define NPAIR (BB * KK)         // 65536
#define OUT_MAIN (NPAIR * NT)   // 131072

// Scratch: per-row projections P[b*N+n] = {z.W0[:,0], z.W0[:,1], z.W1[:,0], z.W1[:,1]}
// where W0 = W[0:D,:], W1 = W[D:2D,:]. 36864 * 16B = 576 KB (static device global,
// allocation-guard safe).
__device__ float4 g_P[ROWS];

// Kernel 1: skinny projection pass. One warp per row, 8 rows per 256-thread block.
// Reads z exactly once (113 MB streaming) -> DRAM-bound.
__global__ __launch_bounds__(256) void partvit_project_kernel(
    const float* __restrict__ z, const float* __restrict__ W) {
    // Rearranged W table: Ws[d] = {W[d][0], W[d][1], W[d+D][0], W[d+D][1]}  (12 KB)
    __shared__ float4 Ws[DD];
    int tid = threadIdx.x;
    #pragma unroll
    for (int i = tid; i < DD; i += 256) {
        float4 w;
        w.x = W[2 * i + 0];
        w.y = W[2 * i + 1];
        w.z = W[2 * (i + DD) + 0];
        w.w = W[2 * (i + DD) + 1];
        Ws[i] = w;
    }
    __syncthreads();

    int warp = tid >> 5;
    int lane = tid & 31;
    int row  = blockIdx.x * 8 + warp;          // grid sized exactly: ROWS/8 blocks

    const float4* z4 = reinterpret_cast<const float4*>(z + (size_t)row * DD);

    float s00 = 0.f, s01 = 0.f, s10 = 0.f, s11 = 0.f;
    #pragma unroll
    for (int j = 0; j < DD / 4 / 32; j++) {    // 6 float4s per lane
        int i4 = lane + 32 * j;
        float4 zv = z4[i4];
        float4 w0 = Ws[4 * i4 + 0];
        float4 w1 = Ws[4 * i4 + 1];
        float4 w2 = Ws[4 * i4 + 2];
        float4 w3 = Ws[4 * i4 + 3];
        s00 += zv.x * w0.x + zv.y * w1.x + zv.z * w2.x + zv.w * w3.x;
        s01 += zv.x * w0.y + zv.y * w1.y + zv.z * w2.y + zv.w * w3.y;
        s10 += zv.x * w0.z + zv.y * w1.z + zv.z * w2.z + zv.w * w3.z;
        s11 += zv.x * w0.w + zv.y * w1.w + zv.z * w2.w + zv.w * w3.w;
    }

    #pragma unroll
    for (int off = 16; off; off >>= 1) {
        s00 += __shfl_xor_sync(0xffffffffu, s00, off);
        s01 += __shfl_xor_sync(0xffffffffu, s01, off);
        s10 += __shfl_xor_sync(0xffffffffu, s10, off);
        s11 += __shfl_xor_sync(0xffffffffu, s11, off);
    }
    if (lane == 0) g_P[row] = make_float4(s00, s01, s10, s11);
}

// Kernel 2: gather pairs of projections + bias. One thread per (b,k) pair.
// Indices are INT32 (JAX x64 disabled: randint(dtype=int64) -> int32).
// P fits in L2 (576 KB); random reads stay on-chip.
__global__ __launch_bounds__(256) void partvit_gather_kernel(
    const int* __restrict__ idx, const float* __restrict__ bh,
    float* __restrict__ out, int out_size) {
    int i = blockIdx.x * 256 + threadIdx.x;    // pair id in [0, B*K)
    if (i >= NPAIR) return;
    int b = i >> 10;                            // i / KK

    int2 p = reinterpret_cast<const int2*>(idx)[i];
    // Clamp defensively (indices should already be in [0, N))
    int i0 = min(max(p.x, 0), NN - 1);
    int i1 = min(max(p.y, 0), NN - 1);

    float4 p0 = g_P[b * NN + i0];   // element 0 of pair -> W[0:D] halves (.x,.y)
    float4 p1 = g_P[b * NN + i1];   // element 1 of pair -> W[D:2D] halves (.z,.w)

    float2 o;
    o.x = p0.x + p1.z + bh[0];
    o.y = p0.y + p1.w + bh[1];
    reinterpret_cast<float2*>(out)[i] = o;

    // If the harness flattens the (out, indices) tuple, echo indices as float32.
    if (out_size >= OUT_MAIN + 2 * (i + 1)) {
        out[OUT_MAIN + 2 * i + 0] = (float)p.x;
        out[OUT_MAIN + 2 * i + 1] = (float)p.y;
    }
}

extern "C" void kernel_launch(void* const* d_in, const int* in_sizes, int n_in,
                              void* d_out, int out_size) {
    const float* z   = (const float*)d_in[0];      // [B, N, D] f32
    const int*   idx = (const int*)d_in[1];        // [B, K, 2] i32
    const float* W   = (const float*)d_in[2];      // [2D, NT] f32
    const float* bh  = (const float*)d_in[3];      // [NT] f32
    float* out = (float*)d_out;

    partvit_project_kernel<<<ROWS / 8, 256>>>(z, W);
    partvit_gather_kernel<<<(NPAIR + 255) / 256, 256>>>(idx, bh, out, out_size);
}

// round 3
// speedup vs baseline: 1.5796x; 1.5796x over previous
#include <cuda_runtime.h>

#define BB 64
#define NN 576
#define DD 768
#define KK 1024
#define NT 2
#define ROWS (BB * NN)          // 36864
#define NPAIR (BB * KK)         // 65536
#define OUT_MAIN (NPAIR * NT)   // 131072

// Per-row projections P[b*N+n] = {z.W0[:,0], z.W0[:,1], z.W1[:,0], z.W1[:,1]}
// where W0 = W[0:D,:], W1 = W[D:2D,:]. 576 KB static scratch (guard-safe).
__device__ float4 g_P[ROWS];

// Kernel 1: skinny projection. Warp per 2 rows (grid-stride), weights held in
// REGISTERS (24 float4/lane, fixed because i4 = lane+32j) — no smem in the loop.
__global__ __launch_bounds__(256) void partvit_project_kernel(
    const float* __restrict__ z, const float* __restrict__ W) {
    int lane = threadIdx.x & 31;
    int gw   = (blockIdx.x * blockDim.x + threadIdx.x) >> 5;
    int nw   = (gridDim.x * blockDim.x) >> 5;

    // wr[j][c] = {W[d][0], W[d][1], W[d+D][0], W[d+D][1]} for d = 4*(lane+32j)+c
    float4 wr[6][4];
    #pragma unroll
    for (int j = 0; j < 6; j++) {
        int i4 = lane + 32 * j;
        #pragma unroll
        for (int c = 0; c < 4; c++) {
            int d = 4 * i4 + c;
            wr[j][c] = make_float4(W[2 * d], W[2 * d + 1],
                                   W[2 * (d + DD)], W[2 * (d + DD) + 1]);
        }
    }

    for (int row = gw * 2; row < ROWS; row += nw * 2) {
        const float4* zA = reinterpret_cast<const float4*>(z + (size_t)row * DD);
        const float4* zB = reinterpret_cast<const float4*>(z + (size_t)(row + 1) * DD);

        float a00 = 0.f, a01 = 0.f, a10 = 0.f, a11 = 0.f;
        float b00 = 0.f, b01 = 0.f, b10 = 0.f, b11 = 0.f;
        #pragma unroll
        for (int j = 0; j < 6; j++) {
            int i4 = lane + 32 * j;
            float4 za = zA[i4];
            float4 zb = zB[i4];
            a00 += za.x * wr[j][0].x + za.y * wr[j][1].x + za.z * wr[j][2].x + za.w * wr[j][3].x;
            a01 += za.x * wr[j][0].y + za.y * wr[j][1].y + za.z * wr[j][2].y + za.w * wr[j][3].y;
            a10 += za.x * wr[j][0].z + za.y * wr[j][1].z + za.z * wr[j][2].z + za.w * wr[j][3].z;
            a11 += za.x * wr[j][0].w + za.y * wr[j][1].w + za.z * wr[j][2].w + za.w * wr[j][3].w;
            b00 += zb.x * wr[j][0].x + zb.y * wr[j][1].x + zb.z * wr[j][2].x + zb.w * wr[j][3].x;
            b01 += zb.x * wr[j][0].y + zb.y * wr[j][1].y + zb.z * wr[j][2].y + zb.w * wr[j][3].y;
            b10 += zb.x * wr[j][0].z + zb.y * wr[j][1].z + zb.z * wr[j][2].z + zb.w * wr[j][3].z;
            b11 += zb.x * wr[j][0].w + zb.y * wr[j][1].w + zb.z * wr[j][2].w + zb.w * wr[j][3].w;
        }

        #pragma unroll
        for (int off = 16; off; off >>= 1) {
            a00 += __shfl_xor_sync(0xffffffffu, a00, off);
            a01 += __shfl_xor_sync(0xffffffffu, a01, off);
            a10 += __shfl_xor_sync(0xffffffffu, a10, off);
            a11 += __shfl_xor_sync(0xffffffffu, a11, off);
            b00 += __shfl_xor_sync(0xffffffffu, b00, off);
            b01 += __shfl_xor_sync(0xffffffffu, b01, off);
            b10 += __shfl_xor_sync(0xffffffffu, b10, off);
            b11 += __shfl_xor_sync(0xffffffffu, b11, off);
        }
        if (lane == 0) {
            g_P[row]     = make_float4(a00, a01, a10, a11);
            g_P[row + 1] = make_float4(b00, b01, b10, b11);
        }
    }
}

// Kernel 2: gather 2 pairs per thread (int4 idx load -> 4 independent P gathers
// from L2-resident table, float4 store). Indices are int32.
__global__ __launch_bounds__(128) void partvit_gather_kernel(
    const int* __restrict__ idx, const float* __restrict__ bh,
    float* __restrict__ out, int out_size) {
    int t = blockIdx.x * 128 + threadIdx.x;   // handles pairs 2t, 2t+1
    if (t >= NPAIR / 2) return;

    int4 p = reinterpret_cast<const int4*>(idx)[t];
    int pair0 = 2 * t;
    int b0 = pair0 >> 10;            // pair0 / KK
    int b1 = (pair0 + 1) >> 10;

    float4 pa0 = g_P[b0 * NN + min(max(p.x, 0), NN - 1)];
    float4 pa1 = g_P[b0 * NN + min(max(p.y, 0), NN - 1)];
    float4 pb0 = g_P[b1 * NN + min(max(p.z, 0), NN - 1)];
    float4 pb1 = g_P[b1 * NN + min(max(p.w, 0), NN - 1)];

    float bh0 = bh[0], bh1 = bh[1];
    float4 o;
    o.x = pa0.x + pa1.z + bh0;
    o.y = pa0.y + pa1.w + bh1;
    o.z = pb0.x + pb1.z + bh0;
    o.w = pb0.y + pb1.w + bh1;
    reinterpret_cast<float4*>(out)[t] = o;

    // If the harness flattens the (out, indices) tuple, echo indices as f32.
    if (out_size >= OUT_MAIN + 2 * NPAIR) {
        float4 e = make_float4((float)p.x, (float)p.y, (float)p.z, (float)p.w);
        reinterpret_cast<float4*>(out + OUT_MAIN)[t] = e;
    }
}

extern "C" void kernel_launch(void* const* d_in, const int* in_sizes, int n_in,
                              void* d_out, int out_size) {
    const float* z   = (const float*)d_in[0];      // [B, N, D] f32
    const int*   idx = (const int*)d_in[1];        // [B, K, 2] i32
    const float* W   = (const float*)d_in[2];      // [2D, NT] f32
    const float* bh  = (const float*)d_in[3];      // [NT] f32
    float* out = (float*)d_out;

    // ~2 blocks/SM, 2368 warps -> ~8 row-pairs per warp (weights amortized)
    partvit_project_kernel<<<296, 256>>>(z, W);
    partvit_gather_kernel<<<(NPAIR / 2 + 127) / 128, 128>>>(idx, bh, out, out_size);
}